// round 7
// baseline (speedup 1.0000x reference)
#include <cuda_runtime.h>
#include <cuda_bf16.h>
#include <cstdint>

// Problem constants
#define N_NODES 50000
#define D_FEAT  128
#define K_TOT   256
#define MT      128
#define NCTA    ((N_NODES + MT - 1) / MT)   // 391
#define TILE_B  16384                        // one [128 x 64] bf16 tile image

// X tile images: per gemm-CTA b, 4 k-tiles (kt0/1 = feat, kt2/3 = agg), hi & lo.
__device__ __align__(16) uint8_t g_xh_img[(size_t)NCTA * 4 * TILE_B];
__device__ __align__(16) uint8_t g_xl_img[(size_t)NCTA * 4 * TILE_B];
__device__ __align__(16) uint8_t g_Wh_img[4 * TILE_B];
__device__ __align__(16) uint8_t g_Wl_img[4 * TILE_B];
__device__ int g_row_ptr[N_NODES + 1];

// ===========================================================================
// Helpers
// ===========================================================================
__device__ __forceinline__ uint32_t smem_u32(const void* p) {
    uint32_t a;
    asm("{ .reg .u64 t; cvta.to.shared.u64 t, %1; cvt.u32.u64 %0, t; }"
        : "=r"(a) : "l"(p));
    return a;
}
#define SWZ128(off) ((off) ^ (((off) >> 3) & 0x70))

__device__ __forceinline__ uint32_t pack_bf16x2(float a, float b) {
    __nv_bfloat162 h = __floats2bfloat162_rn(a, b);
    return *reinterpret_cast<uint32_t*>(&h);
}
__device__ __forceinline__ void ldsm_x4(uint32_t r[4], uint32_t addr) {
    asm volatile("ldmatrix.sync.aligned.m8n8.x4.shared.b16 {%0,%1,%2,%3}, [%4];"
                 : "=r"(r[0]), "=r"(r[1]), "=r"(r[2]), "=r"(r[3]) : "r"(addr));
}
__device__ __forceinline__ void mma_bf16(float c[4], const uint32_t a[4],
                                         uint32_t b0, uint32_t b1) {
    asm volatile(
        "mma.sync.aligned.m16n8k16.row.col.f32.bf16.bf16.f32 "
        "{%0,%1,%2,%3}, {%4,%5,%6,%7}, {%8,%9}, {%0,%1,%2,%3};"
        : "+f"(c[0]), "+f"(c[1]), "+f"(c[2]), "+f"(c[3])
        : "r"(a[0]), "r"(a[1]), "r"(a[2]), "r"(a[3]), "r"(b0), "r"(b1));
}
__device__ __forceinline__ void cp_async16(uint32_t smem, const void* gmem) {
    asm volatile("cp.async.cg.shared.global [%0], [%1], 16;\n"
                 :: "r"(smem), "l"(gmem));
}
__device__ __forceinline__ void cp_commit() {
    asm volatile("cp.async.commit_group;\n" ::);
}
template <int N>
__device__ __forceinline__ void cp_wait() {
    asm volatile("cp.async.wait_group %0;\n" :: "n"(N));
}
// fp32 -> bf16 hi/lo split of a float4
__device__ __forceinline__ void split4(float4 v, uint2& hi, uint2& lo) {
    float hx = __bfloat162float(__float2bfloat16(v.x));
    float hy = __bfloat162float(__float2bfloat16(v.y));
    float hz = __bfloat162float(__float2bfloat16(v.z));
    float hw = __bfloat162float(__float2bfloat16(v.w));
    hi = make_uint2(pack_bf16x2(v.x, v.y), pack_bf16x2(v.z, v.w));
    lo = make_uint2(pack_bf16x2(v.x - hx, v.y - hy),
                    pack_bf16x2(v.z - hz, v.w - hw));
}

// ===========================================================================
// Kernel 0: row_ptr via vectorized edge scan (4 edges/thread).
// ===========================================================================
__global__ __launch_bounds__(256) void rowptr_kernel(
    const int* __restrict__ dst, int n_nodes, int n_edges)
{
    int e4 = blockIdx.x * blockDim.x + threadIdx.x;
    int e0 = e4 * 4;
    if (e0 >= n_edges) return;
    int v0, v1, v2, v3;
    if (e0 + 3 < n_edges) {
        int4 d = __ldg(reinterpret_cast<const int4*>(dst) + e4);
        v0 = d.x; v1 = d.y; v2 = d.z; v3 = d.w;
    } else {
        v0 = __ldg(dst + e0);
        v1 = (e0 + 1 < n_edges) ? __ldg(dst + e0 + 1) : v0;
        v2 = (e0 + 2 < n_edges) ? __ldg(dst + e0 + 2) : v1;
        v3 = (e0 + 3 < n_edges) ? __ldg(dst + e0 + 3) : v2;
    }
    int dp = (e0 == 0) ? -1 : __ldg(dst + e0 - 1);
    int vals[5] = {dp, v0, v1, v2, v3};
#pragma unroll
    for (int j = 0; j < 4; ++j)
        if (e0 + j < n_edges)
            for (int v = vals[j] + 1; v <= vals[j + 1]; ++v)
                g_row_ptr[v] = e0 + j;
    if (e0 + 4 >= n_edges) {
        int last = vals[4 - (e0 + 4 - n_edges)];
        for (int v = last + 1; v <= n_nodes; ++v) g_row_ptr[v] = n_edges;
    }
}

// ===========================================================================
// Kernel 1 (fused): [0,aggb) agg reduction -> agg images (kt2/3)
//                   [aggb,aggb+fpb) feat -> feat images (kt0/1)
//                   [aggb+fpb, +16) W -> W images
// ===========================================================================
__global__ __launch_bounds__(256) void prep_kernel(
    const float4* __restrict__ feat4,
    const float*  __restrict__ affine,
    const int*    __restrict__ src,
    const float*  __restrict__ W,
    int n_nodes, int aggb, int fpb)
{
    const int bid = blockIdx.x;
    const int tid = threadIdx.x;

    if (bid < aggb) {
        // ---- aggregation: warp per node ----
        int warp = (bid * 256 + tid) >> 5;
        int lane = tid & 31;
        if (warp >= n_nodes) return;

        int e  = __ldg(&g_row_ptr[warp]);
        int e1 = __ldg(&g_row_ptr[warp + 1]);

        float4 acc0 = make_float4(0.f, 0.f, 0.f, 0.f);
        float4 acc1 = make_float4(0.f, 0.f, 0.f, 0.f);

        for (; e + 4 <= e1; e += 4) {
            int   s0 = __ldg(src + e + 0), s1 = __ldg(src + e + 1);
            int   s2 = __ldg(src + e + 2), s3 = __ldg(src + e + 3);
            float a0 = __ldg(affine + e + 0), a1 = __ldg(affine + e + 1);
            float a2 = __ldg(affine + e + 2), a3 = __ldg(affine + e + 3);
            float4 f0 = __ldg(feat4 + (size_t)s0 * 32 + lane);
            float4 f1 = __ldg(feat4 + (size_t)s1 * 32 + lane);
            float4 f2 = __ldg(feat4 + (size_t)s2 * 32 + lane);
            float4 f3 = __ldg(feat4 + (size_t)s3 * 32 + lane);
            acc0.x = fmaf(f0.x, a0, acc0.x); acc0.y = fmaf(f0.y, a0, acc0.y);
            acc0.z = fmaf(f0.z, a0, acc0.z); acc0.w = fmaf(f0.w, a0, acc0.w);
            acc1.x = fmaf(f1.x, a1, acc1.x); acc1.y = fmaf(f1.y, a1, acc1.y);
            acc1.z = fmaf(f1.z, a1, acc1.z); acc1.w = fmaf(f1.w, a1, acc1.w);
            acc0.x = fmaf(f2.x, a2, acc0.x); acc0.y = fmaf(f2.y, a2, acc0.y);
            acc0.z = fmaf(f2.z, a2, acc0.z); acc0.w = fmaf(f2.w, a2, acc0.w);
            acc1.x = fmaf(f3.x, a3, acc1.x); acc1.y = fmaf(f3.y, a3, acc1.y);
            acc1.z = fmaf(f3.z, a3, acc1.z); acc1.w = fmaf(f3.w, a3, acc1.w);
        }
        for (; e < e1; ++e) {
            int   s = __ldg(src + e);
            float a = __ldg(affine + e);
            float4 f = __ldg(feat4 + (size_t)s * 32 + lane);
            acc0.x = fmaf(f.x, a, acc0.x); acc0.y = fmaf(f.y, a, acc0.y);
            acc0.z = fmaf(f.z, a, acc0.z); acc0.w = fmaf(f.w, a, acc0.w);
        }
        float4 r = make_float4(acc0.x + acc1.x, acc0.y + acc1.y,
                               acc0.z + acc1.z, acc0.w + acc1.w);
        uint2 hi, lo;
        split4(r, hi, lo);
        int b   = warp >> 7;
        int row = warp & 127;
        int kl  = lane * 4;
        int t   = kl >> 6;               // -> kt 2/3
        int kc  = kl & 63;
        uint32_t off  = SWZ128((uint32_t)(row * 128 + kc * 2));
        size_t   base = ((size_t)b * 4 + 2 + t) * TILE_B;
        *reinterpret_cast<uint2*>(g_xh_img + base + off) = hi;
        *reinterpret_cast<uint2*>(g_xl_img + base + off) = lo;
    } else if (bid < aggb + fpb) {
        // ---- featprep: 4 float4 per thread ----
        int base = (bid - aggb) * 1024 + tid;
        int total = n_nodes * 32;
#pragma unroll
        for (int i = 0; i < 4; ++i) {
            int idx = base + i * 256;
            if (idx < total) {
                int v  = idx >> 5;
                int c4 = idx & 31;
                float4 f = __ldg(feat4 + (size_t)v * 32 + c4);
                uint2 hi, lo;
                split4(f, hi, lo);
                int b   = v >> 7;
                int row = v & 127;
                int k   = c4 * 4;
                int t   = k >> 6;        // -> kt 0/1
                int kc  = k & 63;
                uint32_t off  = SWZ128((uint32_t)(row * 128 + kc * 2));
                size_t   bb   = ((size_t)b * 4 + t) * TILE_B;
                *reinterpret_cast<uint2*>(g_xh_img + bb + off) = hi;
                *reinterpret_cast<uint2*>(g_xl_img + bb + off) = lo;
            }
        }
    } else {
        // ---- wprep ----
        for (int idx = (bid - aggb - fpb) * 256 + tid; idx < K_TOT * D_FEAT;
             idx += 16 * 256) {
            int n = idx & 127;
            int k = idx >> 7;
            float w = __ldg(W + (size_t)k * D_FEAT + n);
            __nv_bfloat16 h = __float2bfloat16(w);
            __nv_bfloat16 l = __float2bfloat16(w - __bfloat162float(h));
            int kt = k >> 6;
            int kc = k & 63;
            uint32_t off = SWZ128((uint32_t)(n * 128 + kc * 2));
            *reinterpret_cast<__nv_bfloat16*>(g_Wh_img + kt * TILE_B + off) = h;
            *reinterpret_cast<__nv_bfloat16*>(g_Wl_img + kt * TILE_B + off) = l;
        }
    }
}

// ===========================================================================
// Kernel 2: pure-streaming split-bf16 HMMA GEMM.
// 512 threads, 16 warps (4m x 4n), warp tile 32x32. Double-buffered 64 KB
// stages (X hi/lo 32 KB + W hi/lo 32 KB) via cp.async. No conversion.
// ===========================================================================
#define XOFF(buf) ((buf) * 32768u)
#define WOFF(buf) (65536u + (buf) * 32768u)
#define SM_TOTAL  131072

__device__ __forceinline__ void mma_tile32(
    uint32_t xh, uint32_t xl, uint32_t wh, uint32_t wl,
    float c[2][4][4], int lane, int wm, int wn)
{
#pragma unroll
    for (int ks = 0; ks < 4; ++ks) {
        uint32_t ah[2][4], al[2][4];
#pragma unroll
        for (int t = 0; t < 2; ++t) {
            int row = wm * 32 + t * 16 + (lane & 15);
            uint32_t off = SWZ128((uint32_t)(row * 128 + ks * 32 + (lane >> 4) * 16));
            ldsm_x4(ah[t], xh + off);
            ldsm_x4(al[t], xl + off);
        }
        int bg    = lane >> 3;
        int bn_in = ((bg >> 1) << 3) + (lane & 7);
        int bk    = ks * 32 + (bg & 1) * 16;

        uint32_t bfr[2][4];
#pragma unroll
        for (int j = 0; j < 2; ++j) {
            int n = wn * 32 + j * 16 + bn_in;
            ldsm_x4(bfr[j], wh + SWZ128((uint32_t)(n * 128 + bk)));
        }
#pragma unroll
        for (int t = 0; t < 2; ++t)
#pragma unroll
            for (int j = 0; j < 2; ++j) {
                mma_bf16(c[t][2 * j + 0], ah[t], bfr[j][0], bfr[j][1]);
                mma_bf16(c[t][2 * j + 1], ah[t], bfr[j][2], bfr[j][3]);
                mma_bf16(c[t][2 * j + 0], al[t], bfr[j][0], bfr[j][1]);
                mma_bf16(c[t][2 * j + 1], al[t], bfr[j][2], bfr[j][3]);
            }
#pragma unroll
        for (int j = 0; j < 2; ++j) {
            int n = wn * 32 + j * 16 + bn_in;
            ldsm_x4(bfr[j], wl + SWZ128((uint32_t)(n * 128 + bk)));
        }
#pragma unroll
        for (int t = 0; t < 2; ++t)
#pragma unroll
            for (int j = 0; j < 2; ++j) {
                mma_bf16(c[t][2 * j + 0], ah[t], bfr[j][0], bfr[j][1]);
                mma_bf16(c[t][2 * j + 1], ah[t], bfr[j][2], bfr[j][3]);
            }
    }
}

__global__ __launch_bounds__(512) void gemm_kernel(
    const float* __restrict__ bias,
    float*       __restrict__ out,
    int M)
{
    extern __shared__ char smem[];
    const uint32_t sb = smem_u32(smem);
    const int tid  = threadIdx.x;
    const int lane = tid & 31;
    const int wid  = tid >> 5;
    const int wm   = wid >> 2;       // 0..3
    const int wn   = wid & 3;        // 0..3
    const int m0   = blockIdx.x * MT;
    const int b    = blockIdx.x;

    // stage fetch: X (hi+lo) + W (hi+lo), 2048 x 16B lines, 512 threads
    auto prefetch = [&](int kt, int buf) {
        size_t xb = ((size_t)b * 4 + kt) * TILE_B;
        size_t wb = (size_t)kt * TILE_B;
#pragma unroll
        for (int j = 0; j < 2; ++j) {
            uint32_t o = (uint32_t)(j * 512 + tid) * 16;
            cp_async16(sb + XOFF(buf) + o,          g_xh_img + xb + o);
            cp_async16(sb + XOFF(buf) + 16384 + o,  g_xl_img + xb + o);
            cp_async16(sb + WOFF(buf) + o,          g_Wh_img + wb + o);
            cp_async16(sb + WOFF(buf) + 16384 + o,  g_Wl_img + wb + o);
        }
        cp_commit();
    };

    float c[2][4][4];
#pragma unroll
    for (int t = 0; t < 2; ++t)
#pragma unroll
        for (int j = 0; j < 4; ++j)
#pragma unroll
            for (int q = 0; q < 4; ++q) c[t][j][q] = 0.f;

    prefetch(0, 0);
#pragma unroll
    for (int kt = 0; kt < 4; ++kt) {
        const int buf = kt & 1;
        if (kt < 3) prefetch(kt + 1, buf ^ 1);
        if (kt < 3) cp_wait<1>(); else cp_wait<0>();
        __syncthreads();
        mma_tile32(sb + XOFF(buf), sb + XOFF(buf) + 16384,
                   sb + WOFF(buf), sb + WOFF(buf) + 16384,
                   c, lane, wm, wn);
        __syncthreads();   // all reads of buf done before kt+2 overwrites it
    }

    // ---- epilogue: bias + store ----
#pragma unroll
    for (int t = 0; t < 2; ++t) {
#pragma unroll
        for (int j = 0; j < 4; ++j) {
            int col = wn * 32 + (j >> 1) * 16 + (j & 1) * 8 + (lane & 3) * 2;
            float b0 = __ldg(bias + col);
            float b1 = __ldg(bias + col + 1);
            int r0 = m0 + wm * 32 + t * 16 + (lane >> 2);
            int r1 = r0 + 8;
            if (r0 < M) {
                float2 o = make_float2(c[t][j][0] + b0, c[t][j][1] + b1);
                *reinterpret_cast<float2*>(out + (size_t)r0 * D_FEAT + col) = o;
            }
            if (r1 < M) {
                float2 o = make_float2(c[t][j][2] + b0, c[t][j][3] + b1);
                *reinterpret_cast<float2*>(out + (size_t)r1 * D_FEAT + col) = o;
            }
        }
    }
}

// ===========================================================================
// Launch
// ===========================================================================
extern "C" void kernel_launch(void* const* d_in, const int* in_sizes, int n_in,
                              void* d_out, int out_size)
{
    const float* feat   = (const float*)d_in[0];
    const float* affine = (const float*)d_in[1];
    const int*   src    = (const int*)  d_in[2];
    const int*   dst    = (const int*)  d_in[3];
    const float* W      = (const float*)d_in[4];
    const float* bias   = (const float*)d_in[5];
    float*       out    = (float*)d_out;

    const int n_nodes = in_sizes[0] / D_FEAT;
    const int n_edges = in_sizes[1];

    cudaFuncSetAttribute(gemm_kernel,
                         cudaFuncAttributeMaxDynamicSharedMemorySize, SM_TOTAL);

    int e4 = (n_edges + 3) / 4;
    rowptr_kernel<<<(e4 + 255) / 256, 256>>>(dst, n_nodes, n_edges);

    int aggb = (n_nodes * 32 + 255) / 256;         // agg blocks
    int fpb  = (n_nodes * 32 + 1023) / 1024;       // featprep blocks
    prep_kernel<<<aggb + fpb + 16, 256>>>(
        reinterpret_cast<const float4*>(feat), affine, src, W,
        n_nodes, aggb, fpb);

    gemm_kernel<<<(n_nodes + MT - 1) / MT, 512, SM_TOTAL>>>(bias, out, n_nodes);
}

// round 8
// speedup vs baseline: 1.2195x; 1.2195x over previous
#include <cuda_runtime.h>
#include <cuda_fp16.h>
#include <cstdint>

// Problem constants
#define N_NODES 50000
#define D_FEAT  128
#define K_TOT   256
#define MT      128
#define NCTA    ((N_NODES + MT - 1) / MT)   // 391
#define TILE_B  16384                        // one [128 x 64] fp16 tile image

// X tile images (fp16 hi only): per gemm-CTA b, kt0/1 = feat, kt2/3 = agg.
__device__ __align__(16) uint8_t g_xh_img[(size_t)NCTA * 4 * TILE_B];
__device__ __align__(16) uint8_t g_Wh_img[4 * TILE_B];
__device__ __align__(16) uint8_t g_Wl_img[4 * TILE_B];
__device__ int g_row_ptr[N_NODES + 1];

// ===========================================================================
// Helpers
// ===========================================================================
__device__ __forceinline__ uint32_t smem_u32(const void* p) {
    uint32_t a;
    asm("{ .reg .u64 t; cvta.to.shared.u64 t, %1; cvt.u32.u64 %0, t; }"
        : "=r"(a) : "l"(p));
    return a;
}
#define SWZ128(off) ((off) ^ (((off) >> 3) & 0x70))

__device__ __forceinline__ uint32_t pack_h2(float a, float b) {
    __half2 h = __floats2half2_rn(a, b);
    return *reinterpret_cast<uint32_t*>(&h);
}
__device__ __forceinline__ void ldsm_x4(uint32_t r[4], uint32_t addr) {
    asm volatile("ldmatrix.sync.aligned.m8n8.x4.shared.b16 {%0,%1,%2,%3}, [%4];"
                 : "=r"(r[0]), "=r"(r[1]), "=r"(r[2]), "=r"(r[3]) : "r"(addr));
}
__device__ __forceinline__ void mma_f16(float c[4], const uint32_t a[4],
                                        uint32_t b0, uint32_t b1) {
    asm volatile(
        "mma.sync.aligned.m16n8k16.row.col.f32.f16.f16.f32 "
        "{%0,%1,%2,%3}, {%4,%5,%6,%7}, {%8,%9}, {%0,%1,%2,%3};"
        : "+f"(c[0]), "+f"(c[1]), "+f"(c[2]), "+f"(c[3])
        : "r"(a[0]), "r"(a[1]), "r"(a[2]), "r"(a[3]), "r"(b0), "r"(b1));
}
__device__ __forceinline__ void cp_async16(uint32_t smem, const void* gmem) {
    asm volatile("cp.async.cg.shared.global [%0], [%1], 16;\n"
                 :: "r"(smem), "l"(gmem));
}
__device__ __forceinline__ void cp_commit() {
    asm volatile("cp.async.commit_group;\n" ::);
}
template <int N>
__device__ __forceinline__ void cp_wait() {
    asm volatile("cp.async.wait_group %0;\n" :: "n"(N));
}
// fp32 float4 -> fp16x4 (hi only)
__device__ __forceinline__ uint2 hi4(float4 v) {
    return make_uint2(pack_h2(v.x, v.y), pack_h2(v.z, v.w));
}

// ===========================================================================
// Kernel 0: row_ptr via vectorized edge scan (4 edges/thread).
// ===========================================================================
__global__ __launch_bounds__(256) void rowptr_kernel(
    const int* __restrict__ dst, int n_nodes, int n_edges)
{
    int e4 = blockIdx.x * blockDim.x + threadIdx.x;
    int e0 = e4 * 4;
    if (e0 >= n_edges) return;
    int v0, v1, v2, v3;
    if (e0 + 3 < n_edges) {
        int4 d = __ldg(reinterpret_cast<const int4*>(dst) + e4);
        v0 = d.x; v1 = d.y; v2 = d.z; v3 = d.w;
    } else {
        v0 = __ldg(dst + e0);
        v1 = (e0 + 1 < n_edges) ? __ldg(dst + e0 + 1) : v0;
        v2 = (e0 + 2 < n_edges) ? __ldg(dst + e0 + 2) : v1;
        v3 = (e0 + 3 < n_edges) ? __ldg(dst + e0 + 3) : v2;
    }
    int dp = (e0 == 0) ? -1 : __ldg(dst + e0 - 1);
    int vals[5] = {dp, v0, v1, v2, v3};
#pragma unroll
    for (int j = 0; j < 4; ++j)
        if (e0 + j < n_edges)
            for (int v = vals[j] + 1; v <= vals[j + 1]; ++v)
                g_row_ptr[v] = e0 + j;
    if (e0 + 4 >= n_edges) {
        int last = vals[4 - (e0 + 4 - n_edges)];
        for (int v = last + 1; v <= n_nodes; ++v) g_row_ptr[v] = n_edges;
    }
}

// ===========================================================================
// Kernel 1 (fused): [0,aggb) agg -> X images kt2/3 (fp16)
//                   [aggb,aggb+fpb) feat -> X images kt0/1 (fp16)
//                   [aggb+fpb, +16) W -> W hi/lo images
// ===========================================================================
__global__ __launch_bounds__(256) void prep_kernel(
    const float4* __restrict__ feat4,
    const float*  __restrict__ affine,
    const int*    __restrict__ src,
    const float*  __restrict__ W,
    int n_nodes, int aggb, int fpb)
{
    const int bid = blockIdx.x;
    const int tid = threadIdx.x;

    if (bid < aggb) {
        // ---- aggregation: warp per node ----
        int warp = (bid * 256 + tid) >> 5;
        int lane = tid & 31;
        if (warp >= n_nodes) return;

        int e  = __ldg(&g_row_ptr[warp]);
        int e1 = __ldg(&g_row_ptr[warp + 1]);

        float4 acc0 = make_float4(0.f, 0.f, 0.f, 0.f);
        float4 acc1 = make_float4(0.f, 0.f, 0.f, 0.f);

        for (; e + 4 <= e1; e += 4) {
            int   s0 = __ldg(src + e + 0), s1 = __ldg(src + e + 1);
            int   s2 = __ldg(src + e + 2), s3 = __ldg(src + e + 3);
            float a0 = __ldg(affine + e + 0), a1 = __ldg(affine + e + 1);
            float a2 = __ldg(affine + e + 2), a3 = __ldg(affine + e + 3);
            float4 f0 = __ldg(feat4 + (size_t)s0 * 32 + lane);
            float4 f1 = __ldg(feat4 + (size_t)s1 * 32 + lane);
            float4 f2 = __ldg(feat4 + (size_t)s2 * 32 + lane);
            float4 f3 = __ldg(feat4 + (size_t)s3 * 32 + lane);
            acc0.x = fmaf(f0.x, a0, acc0.x); acc0.y = fmaf(f0.y, a0, acc0.y);
            acc0.z = fmaf(f0.z, a0, acc0.z); acc0.w = fmaf(f0.w, a0, acc0.w);
            acc1.x = fmaf(f1.x, a1, acc1.x); acc1.y = fmaf(f1.y, a1, acc1.y);
            acc1.z = fmaf(f1.z, a1, acc1.z); acc1.w = fmaf(f1.w, a1, acc1.w);
            acc0.x = fmaf(f2.x, a2, acc0.x); acc0.y = fmaf(f2.y, a2, acc0.y);
            acc0.z = fmaf(f2.z, a2, acc0.z); acc0.w = fmaf(f2.w, a2, acc0.w);
            acc1.x = fmaf(f3.x, a3, acc1.x); acc1.y = fmaf(f3.y, a3, acc1.y);
            acc1.z = fmaf(f3.z, a3, acc1.z); acc1.w = fmaf(f3.w, a3, acc1.w);
        }
        for (; e < e1; ++e) {
            int   s = __ldg(src + e);
            float a = __ldg(affine + e);
            float4 f = __ldg(feat4 + (size_t)s * 32 + lane);
            acc0.x = fmaf(f.x, a, acc0.x); acc0.y = fmaf(f.y, a, acc0.y);
            acc0.z = fmaf(f.z, a, acc0.z); acc0.w = fmaf(f.w, a, acc0.w);
        }
        float4 r = make_float4(acc0.x + acc1.x, acc0.y + acc1.y,
                               acc0.z + acc1.z, acc0.w + acc1.w);
        int b   = warp >> 7;
        int row = warp & 127;
        int kl  = lane * 4;
        int t   = kl >> 6;               // -> kt 2/3
        int kc  = kl & 63;
        uint32_t off  = SWZ128((uint32_t)(row * 128 + kc * 2));
        size_t   base = ((size_t)b * 4 + 2 + t) * TILE_B;
        *reinterpret_cast<uint2*>(g_xh_img + base + off) = hi4(r);
    } else if (bid < aggb + fpb) {
        // ---- featprep: 4 float4 per thread ----
        int base = (bid - aggb) * 1024 + tid;
        int total = n_nodes * 32;
#pragma unroll
        for (int i = 0; i < 4; ++i) {
            int idx = base + i * 256;
            if (idx < total) {
                int v  = idx >> 5;
                int c4 = idx & 31;
                float4 f = __ldg(feat4 + (size_t)v * 32 + c4);
                int b   = v >> 7;
                int row = v & 127;
                int k   = c4 * 4;
                int t   = k >> 6;        // -> kt 0/1
                int kc  = k & 63;
                uint32_t off = SWZ128((uint32_t)(row * 128 + kc * 2));
                size_t   bb  = ((size_t)b * 4 + t) * TILE_B;
                *reinterpret_cast<uint2*>(g_xh_img + bb + off) = hi4(f);
            }
        }
    } else {
        // ---- wprep: fp16 hi/lo ----
        for (int idx = (bid - aggb - fpb) * 256 + tid; idx < K_TOT * D_FEAT;
             idx += 16 * 256) {
            int n = idx & 127;
            int k = idx >> 7;
            float w = __ldg(W + (size_t)k * D_FEAT + n);
            __half h = __float2half(w);
            __half l = __float2half(w - __half2float(h));
            int kt = k >> 6;
            int kc = k & 63;
            uint32_t off = SWZ128((uint32_t)(n * 128 + kc * 2));
            *reinterpret_cast<__half*>(g_Wh_img + kt * TILE_B + off) = h;
            *reinterpret_cast<__half*>(g_Wl_img + kt * TILE_B + off) = l;
        }
    }
}

// ===========================================================================
// Kernel 2: pure-streaming 2-pass fp16 HMMA GEMM (AhBh + AhBl).
// 512 threads, 16 warps (4m x 4n), warp tile 32x32. All 4 K-stages
// (X hi 16KB + W hi 16KB + W lo 16KB = 48KB each) prefetched upfront.
// ===========================================================================
#define STAGE_B   49152u
#define SM_TOTAL  (4 * 49152)     // 196608

__device__ __forceinline__ void mma_tile32(
    uint32_t xh, uint32_t wh, uint32_t wl,
    float c[2][4][4], int lane, int wm, int wn)
{
#pragma unroll
    for (int ks = 0; ks < 4; ++ks) {
        uint32_t ah[2][4];
#pragma unroll
        for (int t = 0; t < 2; ++t) {
            int row = wm * 32 + t * 16 + (lane & 15);
            uint32_t off = SWZ128((uint32_t)(row * 128 + ks * 32 + (lane >> 4) * 16));
            ldsm_x4(ah[t], xh + off);
        }
        int bg    = lane >> 3;
        int bn_in = ((bg >> 1) << 3) + (lane & 7);
        int bk    = ks * 32 + (bg & 1) * 16;

        uint32_t bh[2][4], bl[2][4];
#pragma unroll
        for (int j = 0; j < 2; ++j) {
            int n = wn * 32 + j * 16 + bn_in;
            uint32_t noff = SWZ128((uint32_t)(n * 128 + bk));
            ldsm_x4(bh[j], wh + noff);
            ldsm_x4(bl[j], wl + noff);
        }
#pragma unroll
        for (int t = 0; t < 2; ++t)
#pragma unroll
            for (int j = 0; j < 2; ++j) {
                mma_f16(c[t][2 * j + 0], ah[t], bh[j][0], bh[j][1]);
                mma_f16(c[t][2 * j + 1], ah[t], bh[j][2], bh[j][3]);
                mma_f16(c[t][2 * j + 0], ah[t], bl[j][0], bl[j][1]);
                mma_f16(c[t][2 * j + 1], ah[t], bl[j][2], bl[j][3]);
            }
    }
}

__global__ __launch_bounds__(512) void gemm_kernel(
    const float* __restrict__ bias,
    float*       __restrict__ out,
    int M)
{
    extern __shared__ char smem[];
    const uint32_t sb = smem_u32(smem);
    const int tid  = threadIdx.x;
    const int lane = tid & 31;
    const int wid  = tid >> 5;
    const int wm   = wid >> 2;
    const int wn   = wid & 3;
    const int m0   = blockIdx.x * MT;
    const int b    = blockIdx.x;

    // ---- prologue: prefetch all 4 stages, one commit group each ----
#pragma unroll
    for (int kt = 0; kt < 4; ++kt) {
        size_t xb = ((size_t)b * 4 + kt) * TILE_B;
        size_t wb = (size_t)kt * TILE_B;
#pragma unroll
        for (int j = 0; j < 2; ++j) {
            uint32_t o = (uint32_t)(j * 512 + tid) * 16;
            cp_async16(sb + kt * STAGE_B + o,          g_xh_img + xb + o);
            cp_async16(sb + kt * STAGE_B + 16384 + o,  g_Wh_img + wb + o);
            cp_async16(sb + kt * STAGE_B + 32768 + o,  g_Wl_img + wb + o);
        }
        cp_commit();
    }

    float c[2][4][4];
#pragma unroll
    for (int t = 0; t < 2; ++t)
#pragma unroll
        for (int j = 0; j < 4; ++j)
#pragma unroll
            for (int q = 0; q < 4; ++q) c[t][j][q] = 0.f;

    cp_wait<3>(); __syncthreads();
    mma_tile32(sb + 0 * STAGE_B, sb + 0 * STAGE_B + 16384, sb + 0 * STAGE_B + 32768,
               c, lane, wm, wn);
    cp_wait<2>(); __syncthreads();
    mma_tile32(sb + 1 * STAGE_B, sb + 1 * STAGE_B + 16384, sb + 1 * STAGE_B + 32768,
               c, lane, wm, wn);
    cp_wait<1>(); __syncthreads();
    mma_tile32(sb + 2 * STAGE_B, sb + 2 * STAGE_B + 16384, sb + 2 * STAGE_B + 32768,
               c, lane, wm, wn);
    cp_wait<0>(); __syncthreads();
    mma_tile32(sb + 3 * STAGE_B, sb + 3 * STAGE_B + 16384, sb + 3 * STAGE_B + 32768,
               c, lane, wm, wn);

    // ---- epilogue: bias + store ----
#pragma unroll
    for (int t = 0; t < 2; ++t) {
#pragma unroll
        for (int j = 0; j < 4; ++j) {
            int col = wn * 32 + (j >> 1) * 16 + (j & 1) * 8 + (lane & 3) * 2;
            float b0 = __ldg(bias + col);
            float b1 = __ldg(bias + col + 1);
            int r0 = m0 + wm * 32 + t * 16 + (lane >> 2);
            int r1 = r0 + 8;
            if (r0 < M) {
                float2 o = make_float2(c[t][j][0] + b0, c[t][j][1] + b1);
                *reinterpret_cast<float2*>(out + (size_t)r0 * D_FEAT + col) = o;
            }
            if (r1 < M) {
                float2 o = make_float2(c[t][j][2] + b0, c[t][j][3] + b1);
                *reinterpret_cast<float2*>(out + (size_t)r1 * D_FEAT + col) = o;
            }
        }
    }
}

// ===========================================================================
// Launch
// ===========================================================================
extern "C" void kernel_launch(void* const* d_in, const int* in_sizes, int n_in,
                              void* d_out, int out_size)
{
    const float* feat   = (const float*)d_in[0];
    const float* affine = (const float*)d_in[1];
    const int*   src    = (const int*)  d_in[2];
    const int*   dst    = (const int*)  d_in[3];
    const float* W      = (const float*)d_in[4];
    const float* bias   = (const float*)d_in[5];
    float*       out    = (float*)d_out;

    const int n_nodes = in_sizes[0] / D_FEAT;
    const int n_edges = in_sizes[1];

    cudaFuncSetAttribute(gemm_kernel,
                         cudaFuncAttributeMaxDynamicSharedMemorySize, SM_TOTAL);

    int e4 = (n_edges + 3) / 4;
    rowptr_kernel<<<(e4 + 255) / 256, 256>>>(dst, n_nodes, n_edges);

    int aggb = (n_nodes * 32 + 255) / 256;         // agg blocks
    int fpb  = (n_nodes * 32 + 1023) / 1024;       // featprep blocks
    prep_kernel<<<aggb + fpb + 16, 256>>>(
        reinterpret_cast<const float4*>(feat), affine, src, W,
        n_nodes, aggb, fpb);

    gemm_kernel<<<(n_nodes + MT - 1) / MT, 512, SM_TOTAL>>>(bias, out, n_nodes);
}

// round 9
// speedup vs baseline: 1.2478x; 1.0232x over previous
#include <cuda_runtime.h>
#include <cuda_fp16.h>
#include <cstdint>

// Problem constants
#define N_NODES 50000
#define D_FEAT  128
#define K_TOT   256
#define MT      128
#define NCTA    ((N_NODES + MT - 1) / MT)   // 391
#define TILE_B  16384                        // one [128 x 64] fp16 tile image

// X tile images (fp16): per gemm-CTA b, kt0/1 = feat, kt2/3 = agg.
__device__ __align__(16) uint8_t g_xh_img[(size_t)NCTA * 4 * TILE_B];
__device__ __align__(16) uint8_t g_Wh_img[4 * TILE_B];
__device__ __align__(16) uint8_t g_Wl_img[4 * TILE_B];
__device__ int g_row_ptr[N_NODES + 1];

// ===========================================================================
// Helpers
// ===========================================================================
__device__ __forceinline__ uint32_t smem_u32(const void* p) {
    uint32_t a;
    asm("{ .reg .u64 t; cvta.to.shared.u64 t, %1; cvt.u32.u64 %0, t; }"
        : "=r"(a) : "l"(p));
    return a;
}
#define SWZ128(off) ((off) ^ (((off) >> 3) & 0x70))

__device__ __forceinline__ uint32_t pack_h2(float a, float b) {
    __half2 h = __floats2half2_rn(a, b);
    return *reinterpret_cast<uint32_t*>(&h);
}
__device__ __forceinline__ void ldsm_x4(uint32_t r[4], uint32_t addr) {
    asm volatile("ldmatrix.sync.aligned.m8n8.x4.shared.b16 {%0,%1,%2,%3}, [%4];"
                 : "=r"(r[0]), "=r"(r[1]), "=r"(r[2]), "=r"(r[3]) : "r"(addr));
}
__device__ __forceinline__ void mma_f16(float c[4], const uint32_t a[4],
                                        uint32_t b0, uint32_t b1) {
    asm volatile(
        "mma.sync.aligned.m16n8k16.row.col.f32.f16.f16.f32 "
        "{%0,%1,%2,%3}, {%4,%5,%6,%7}, {%8,%9}, {%0,%1,%2,%3};"
        : "+f"(c[0]), "+f"(c[1]), "+f"(c[2]), "+f"(c[3])
        : "r"(a[0]), "r"(a[1]), "r"(a[2]), "r"(a[3]), "r"(b0), "r"(b1));
}
__device__ __forceinline__ void cp_async16(uint32_t smem, const void* gmem) {
    asm volatile("cp.async.cg.shared.global [%0], [%1], 16;\n"
                 :: "r"(smem), "l"(gmem));
}
__device__ __forceinline__ void cp_commit() {
    asm volatile("cp.async.commit_group;\n" ::);
}
template <int N>
__device__ __forceinline__ void cp_wait() {
    asm volatile("cp.async.wait_group %0;\n" :: "n"(N));
}
__device__ __forceinline__ uint2 hi4(float4 v) {
    return make_uint2(pack_h2(v.x, v.y), pack_h2(v.z, v.w));
}

// ===========================================================================
// Kernel 1 (fused, independent parts):
//   [0, rpb)            row_ptr via vectorized edge scan
//   [rpb, rpb+fpb)      feat -> fp16 X images kt0/1
//   [rpb+fpb, +16)      W -> fp16 hi/lo images
// ===========================================================================
__global__ __launch_bounds__(256) void prep1_kernel(
    const float4* __restrict__ feat4,
    const int*    __restrict__ dst,
    const float*  __restrict__ W,
    int n_nodes, int n_edges, int rpb, int fpb)
{
    const int bid = blockIdx.x;
    const int tid = threadIdx.x;

    if (bid < rpb) {
        // ---- rowptr: 4 edges per thread ----
        int e4 = bid * 256 + tid;
        int e0 = e4 * 4;
        if (e0 >= n_edges) return;
        int v0, v1, v2, v3;
        if (e0 + 3 < n_edges) {
            int4 d = __ldg(reinterpret_cast<const int4*>(dst) + e4);
            v0 = d.x; v1 = d.y; v2 = d.z; v3 = d.w;
        } else {
            v0 = __ldg(dst + e0);
            v1 = (e0 + 1 < n_edges) ? __ldg(dst + e0 + 1) : v0;
            v2 = (e0 + 2 < n_edges) ? __ldg(dst + e0 + 2) : v1;
            v3 = (e0 + 3 < n_edges) ? __ldg(dst + e0 + 3) : v2;
        }
        int dp = (e0 == 0) ? -1 : __ldg(dst + e0 - 1);
        int vals[5] = {dp, v0, v1, v2, v3};
#pragma unroll
        for (int j = 0; j < 4; ++j)
            if (e0 + j < n_edges)
                for (int v = vals[j] + 1; v <= vals[j + 1]; ++v)
                    g_row_ptr[v] = e0 + j;
        if (e0 + 4 >= n_edges) {
            int last = vals[4 - (e0 + 4 - n_edges)];
            for (int v = last + 1; v <= n_nodes; ++v) g_row_ptr[v] = n_edges;
        }
    } else if (bid < rpb + fpb) {
        // ---- featprep: 4 float4 per thread ----
        int base  = (bid - rpb) * 1024 + tid;
        int total = n_nodes * 32;
#pragma unroll
        for (int i = 0; i < 4; ++i) {
            int idx = base + i * 256;
            if (idx < total) {
                int v  = idx >> 5;
                int c4 = idx & 31;
                float4 f = __ldg(feat4 + (size_t)v * 32 + c4);
                int b   = v >> 7;
                int row = v & 127;
                int k   = c4 * 4;
                int t   = k >> 6;        // -> kt 0/1
                int kc  = k & 63;
                uint32_t off = SWZ128((uint32_t)(row * 128 + kc * 2));
                size_t   bb  = ((size_t)b * 4 + t) * TILE_B;
                *reinterpret_cast<uint2*>(g_xh_img + bb + off) = hi4(f);
            }
        }
    } else {
        // ---- wprep: fp16 hi/lo ----
        for (int idx = (bid - rpb - fpb) * 256 + tid; idx < K_TOT * D_FEAT;
             idx += 16 * 256) {
            int n = idx & 127;
            int k = idx >> 7;
            float w = __ldg(W + (size_t)k * D_FEAT + n);
            __half h = __float2half(w);
            __half l = __float2half(w - __half2float(h));
            int kt = k >> 6;
            int kc = k & 63;
            uint32_t off = SWZ128((uint32_t)(n * 128 + kc * 2));
            *reinterpret_cast<__half*>(g_Wh_img + kt * TILE_B + off) = h;
            *reinterpret_cast<__half*>(g_Wl_img + kt * TILE_B + off) = l;
        }
    }
}

// ===========================================================================
// Kernel 2: warp-per-node segmented reduction, gathering fp16 feat from the
// kt0/1 X images (swizzled addressing inlined). 256B per edge, fp32 accum.
// Emits agg as fp16 into X images kt2/3.
// ===========================================================================
__device__ __forceinline__ void acc_edge(float4& acc, const uint8_t* p, float a) {
    uint2 d = *reinterpret_cast<const uint2*>(p);
    float2 f01 = __half22float2(*reinterpret_cast<const __half2*>(&d.x));
    float2 f23 = __half22float2(*reinterpret_cast<const __half2*>(&d.y));
    acc.x = fmaf(f01.x, a, acc.x);
    acc.y = fmaf(f01.y, a, acc.y);
    acc.z = fmaf(f23.x, a, acc.z);
    acc.w = fmaf(f23.y, a, acc.w);
}

__global__ __launch_bounds__(256) void agg_kernel(
    const float* __restrict__ affine,
    const int*   __restrict__ src,
    int n_nodes)
{
    int warp = (blockIdx.x * blockDim.x + threadIdx.x) >> 5;
    int lane = threadIdx.x & 31;
    if (warp >= n_nodes) return;

    int e  = __ldg(&g_row_ptr[warp]);
    int e1 = __ldg(&g_row_ptr[warp + 1]);

    // lane owns k = lane*4 .. lane*4+3  ->  tile t = lane>>4, q = (lane&15)*8
    const uint32_t tq = (uint32_t)(lane >> 4) * TILE_B + (uint32_t)(lane & 15) * 8;

    float4 acc0 = make_float4(0.f, 0.f, 0.f, 0.f);
    float4 acc1 = make_float4(0.f, 0.f, 0.f, 0.f);

    for (; e + 4 <= e1; e += 4) {
        int   s0 = __ldg(src + e + 0), s1 = __ldg(src + e + 1);
        int   s2 = __ldg(src + e + 2), s3 = __ldg(src + e + 3);
        float a0 = __ldg(affine + e + 0), a1 = __ldg(affine + e + 1);
        float a2 = __ldg(affine + e + 2), a3 = __ldg(affine + e + 3);
        const uint8_t* p0 = g_xh_img + ((size_t)(s0 >> 7) * 4) * TILE_B
                            + (uint32_t)(s0 & 127) * 128 + (tq ^ (((uint32_t)s0 & 7) << 4));
        const uint8_t* p1 = g_xh_img + ((size_t)(s1 >> 7) * 4) * TILE_B
                            + (uint32_t)(s1 & 127) * 128 + (tq ^ (((uint32_t)s1 & 7) << 4));
        const uint8_t* p2 = g_xh_img + ((size_t)(s2 >> 7) * 4) * TILE_B
                            + (uint32_t)(s2 & 127) * 128 + (tq ^ (((uint32_t)s2 & 7) << 4));
        const uint8_t* p3 = g_xh_img + ((size_t)(s3 >> 7) * 4) * TILE_B
                            + (uint32_t)(s3 & 127) * 128 + (tq ^ (((uint32_t)s3 & 7) << 4));
        acc_edge(acc0, p0, a0);
        acc_edge(acc1, p1, a1);
        acc_edge(acc0, p2, a2);
        acc_edge(acc1, p3, a3);
    }
    for (; e < e1; ++e) {
        int   s = __ldg(src + e);
        float a = __ldg(affine + e);
        const uint8_t* p = g_xh_img + ((size_t)(s >> 7) * 4) * TILE_B
                           + (uint32_t)(s & 127) * 128 + (tq ^ (((uint32_t)s & 7) << 4));
        acc_edge(acc0, p, a);
    }
    float4 r = make_float4(acc0.x + acc1.x, acc0.y + acc1.y,
                           acc0.z + acc1.z, acc0.w + acc1.w);

    int b   = warp >> 7;
    int row = warp & 127;
    int kl  = lane * 4;
    int t   = kl >> 6;               // -> kt 2/3
    int kc  = kl & 63;
    uint32_t off  = SWZ128((uint32_t)(row * 128 + kc * 2));
    size_t   base = ((size_t)b * 4 + 2 + t) * TILE_B;
    *reinterpret_cast<uint2*>(g_xh_img + base + off) = hi4(r);
}

// ===========================================================================
// Kernel 3: pure-streaming 2-pass fp16 HMMA GEMM (AhBh + AhBl).
// 512 threads, 16 warps (4m x 4n), warp tile 32x32. All 4 K-stages
// (X hi 16KB + W hi 16KB + W lo 16KB = 48KB each) prefetched upfront.
// ===========================================================================
#define STAGE_B   49152u
#define SM_TOTAL  (4 * 49152)     // 196608

__device__ __forceinline__ void mma_tile32(
    uint32_t xh, uint32_t wh, uint32_t wl,
    float c[2][4][4], int lane, int wm, int wn)
{
#pragma unroll
    for (int ks = 0; ks < 4; ++ks) {
        uint32_t ah[2][4];
#pragma unroll
        for (int t = 0; t < 2; ++t) {
            int row = wm * 32 + t * 16 + (lane & 15);
            uint32_t off = SWZ128((uint32_t)(row * 128 + ks * 32 + (lane >> 4) * 16));
            ldsm_x4(ah[t], xh + off);
        }
        int bg    = lane >> 3;
        int bn_in = ((bg >> 1) << 3) + (lane & 7);
        int bk    = ks * 32 + (bg & 1) * 16;

        uint32_t bh[2][4], bl[2][4];
#pragma unroll
        for (int j = 0; j < 2; ++j) {
            int n = wn * 32 + j * 16 + bn_in;
            uint32_t noff = SWZ128((uint32_t)(n * 128 + bk));
            ldsm_x4(bh[j], wh + noff);
            ldsm_x4(bl[j], wl + noff);
        }
#pragma unroll
        for (int t = 0; t < 2; ++t)
#pragma unroll
            for (int j = 0; j < 2; ++j) {
                mma_f16(c[t][2 * j + 0], ah[t], bh[j][0], bh[j][1]);
                mma_f16(c[t][2 * j + 1], ah[t], bh[j][2], bh[j][3]);
                mma_f16(c[t][2 * j + 0], ah[t], bl[j][0], bl[j][1]);
                mma_f16(c[t][2 * j + 1], ah[t], bl[j][2], bl[j][3]);
            }
    }
}

__global__ __launch_bounds__(512) void gemm_kernel(
    const float* __restrict__ bias,
    float*       __restrict__ out,
    int M)
{
    extern __shared__ char smem[];
    const uint32_t sb = smem_u32(smem);
    const int tid  = threadIdx.x;
    const int lane = tid & 31;
    const int wid  = tid >> 5;
    const int wm   = wid >> 2;
    const int wn   = wid & 3;
    const int m0   = blockIdx.x * MT;
    const int b    = blockIdx.x;

#pragma unroll
    for (int kt = 0; kt < 4; ++kt) {
        size_t xb = ((size_t)b * 4 + kt) * TILE_B;
        size_t wb = (size_t)kt * TILE_B;
#pragma unroll
        for (int j = 0; j < 2; ++j) {
            uint32_t o = (uint32_t)(j * 512 + tid) * 16;
            cp_async16(sb + kt * STAGE_B + o,          g_xh_img + xb + o);
            cp_async16(sb + kt * STAGE_B + 16384 + o,  g_Wh_img + wb + o);
            cp_async16(sb + kt * STAGE_B + 32768 + o,  g_Wl_img + wb + o);
        }
        cp_commit();
    }

    float c[2][4][4];
#pragma unroll
    for (int t = 0; t < 2; ++t)
#pragma unroll
        for (int j = 0; j < 4; ++j)
#pragma unroll
            for (int q = 0; q < 4; ++q) c[t][j][q] = 0.f;

    cp_wait<3>(); __syncthreads();
    mma_tile32(sb + 0 * STAGE_B, sb + 0 * STAGE_B + 16384, sb + 0 * STAGE_B + 32768,
               c, lane, wm, wn);
    cp_wait<2>(); __syncthreads();
    mma_tile32(sb + 1 * STAGE_B, sb + 1 * STAGE_B + 16384, sb + 1 * STAGE_B + 32768,
               c, lane, wm, wn);
    cp_wait<1>(); __syncthreads();
    mma_tile32(sb + 2 * STAGE_B, sb + 2 * STAGE_B + 16384, sb + 2 * STAGE_B + 32768,
               c, lane, wm, wn);
    cp_wait<0>(); __syncthreads();
    mma_tile32(sb + 3 * STAGE_B, sb + 3 * STAGE_B + 16384, sb + 3 * STAGE_B + 32768,
               c, lane, wm, wn);

#pragma unroll
    for (int t = 0; t < 2; ++t) {
#pragma unroll
        for (int j = 0; j < 4; ++j) {
            int col = wn * 32 + (j >> 1) * 16 + (j & 1) * 8 + (lane & 3) * 2;
            float b0 = __ldg(bias + col);
            float b1 = __ldg(bias + col + 1);
            int r0 = m0 + wm * 32 + t * 16 + (lane >> 2);
            int r1 = r0 + 8;
            if (r0 < M) {
                float2 o = make_float2(c[t][j][0] + b0, c[t][j][1] + b1);
                *reinterpret_cast<float2*>(out + (size_t)r0 * D_FEAT + col) = o;
            }
            if (r1 < M) {
                float2 o = make_float2(c[t][j][2] + b0, c[t][j][3] + b1);
                *reinterpret_cast<float2*>(out + (size_t)r1 * D_FEAT + col) = o;
            }
        }
    }
}

// ===========================================================================
// Launch
// ===========================================================================
extern "C" void kernel_launch(void* const* d_in, const int* in_sizes, int n_in,
                              void* d_out, int out_size)
{
    const float* feat   = (const float*)d_in[0];
    const float* affine = (const float*)d_in[1];
    const int*   src    = (const int*)  d_in[2];
    const int*   dst    = (const int*)  d_in[3];
    const float* W      = (const float*)d_in[4];
    const float* bias   = (const float*)d_in[5];
    float*       out    = (float*)d_out;

    const int n_nodes = in_sizes[0] / D_FEAT;
    const int n_edges = in_sizes[1];

    cudaFuncSetAttribute(gemm_kernel,
                         cudaFuncAttributeMaxDynamicSharedMemorySize, SM_TOTAL);

    int rpb = ((n_edges + 3) / 4 + 255) / 256;     // rowptr blocks
    int fpb = (n_nodes * 32 + 1023) / 1024;        // featprep blocks
    prep1_kernel<<<rpb + fpb + 16, 256>>>(
        reinterpret_cast<const float4*>(feat), dst, W,
        n_nodes, n_edges, rpb, fpb);

    agg_kernel<<<(n_nodes * 32 + 255) / 256, 256>>>(affine, src, n_nodes);

    gemm_kernel<<<(n_nodes + MT - 1) / MT, 512, SM_TOTAL>>>(bias, out, n_nodes);
}